// round 4
// baseline (speedup 1.0000x reference)
#include <cuda_runtime.h>
#include <math.h>

// ---------------------------------------------------------------------------
// GaussianSceneModel: 1M gaussians -> camera (rgb, depth, alpha) + lidar
// (depth, alpha) via bilinear scatter splatting.
// R4: accumulate into 16B-aligned scratch with red.global.add.v4/v2.f32,
//     finalize is pure streaming scratch->out (no RMW, no out zeroing).
// Projection arithmetic uses explicit IEEE intrinsics to bit-match fp32 ref.
// ---------------------------------------------------------------------------

#define W_IMG   1600
#define H_IMG   900
#define WL_IMG  1024
#define HL_IMG  128
#define CAM_PIX (W_IMG * H_IMG)          // 1,440,000
#define LID_PIX (WL_IMG * HL_IMG)        // 131,072
#define OFF_RGB   0
#define OFF_DEPTH (3 * CAM_PIX)
#define OFF_ALPHA (4 * CAM_PIX)
#define OFF_LD    (5 * CAM_PIX)
#define OFF_LA    (5 * CAM_PIX + LID_PIX)

#define FMIN_F ((float)(-0.4363323129985824))
#define FMAX_F ((float)(0.05235987755982988))
#define FRANGE_F ((float)(0.05235987755982988 + 0.4363323129985824))
#define TWO_PI_F ((float)(6.283185307179586))
#define SIN_FMIN_LO (-0.42261826f - 1e-4f)
#define SIN_FMAX_HI ( 0.05233596f + 1e-4f)
#define NEAR_PLANE 1.0f
#define FAR_PLANE  100.0f
#define EPS 1e-8f

// Scratch accumulators (device globals -- no allocation).
__device__ float4 g_cam4[CAM_PIX];   // (r*w, g*w, b*w, z*w)
__device__ float  g_camA[CAM_PIX];   // sum w
__device__ float2 g_lid2[LID_PIX];   // (r*w, w)

struct Params {
    float w2c[12];
    float w2l[12];
    float fx, fy, cx, cy;
};
__device__ Params g_P;

__device__ __forceinline__ void red_add_v4(float4* addr, float a, float b,
                                           float c, float d) {
    asm volatile("red.global.add.v4.f32 [%0], {%1, %2, %3, %4};"
                 :: "l"(addr), "f"(a), "f"(b), "f"(c), "f"(d) : "memory");
}
__device__ __forceinline__ void red_add_v2(float2* addr, float a, float b) {
    asm volatile("red.global.add.v2.f32 [%0], {%1, %2};"
                 :: "l"(addr), "f"(a), "f"(b) : "memory");
}

__device__ void inv4x4(const float* m, float* invOut) {
    float inv[16];
    inv[0] = m[5]*m[10]*m[15] - m[5]*m[11]*m[14] - m[9]*m[6]*m[15] +
             m[9]*m[7]*m[14] + m[13]*m[6]*m[11] - m[13]*m[7]*m[10];
    inv[4] = -m[4]*m[10]*m[15] + m[4]*m[11]*m[14] + m[8]*m[6]*m[15] -
             m[8]*m[7]*m[14] - m[12]*m[6]*m[11] + m[12]*m[7]*m[10];
    inv[8] = m[4]*m[9]*m[15] - m[4]*m[11]*m[13] - m[8]*m[5]*m[15] +
             m[8]*m[7]*m[13] + m[12]*m[5]*m[11] - m[12]*m[7]*m[9];
    inv[12] = -m[4]*m[9]*m[14] + m[4]*m[10]*m[13] + m[8]*m[5]*m[14] -
              m[8]*m[6]*m[13] - m[12]*m[5]*m[10] + m[12]*m[6]*m[9];
    inv[1] = -m[1]*m[10]*m[15] + m[1]*m[11]*m[14] + m[9]*m[2]*m[15] -
             m[9]*m[3]*m[14] - m[13]*m[2]*m[11] + m[13]*m[3]*m[10];
    inv[5] = m[0]*m[10]*m[15] - m[0]*m[11]*m[14] - m[8]*m[2]*m[15] +
             m[8]*m[3]*m[14] + m[12]*m[2]*m[11] - m[12]*m[3]*m[10];
    inv[9] = -m[0]*m[9]*m[15] + m[0]*m[11]*m[13] + m[8]*m[1]*m[15] -
             m[8]*m[3]*m[13] - m[12]*m[1]*m[11] + m[12]*m[3]*m[9];
    inv[13] = m[0]*m[9]*m[14] - m[0]*m[10]*m[13] - m[8]*m[1]*m[14] +
              m[8]*m[2]*m[13] + m[12]*m[1]*m[10] - m[12]*m[2]*m[9];
    inv[2] = m[1]*m[6]*m[15] - m[1]*m[7]*m[14] - m[5]*m[2]*m[15] +
             m[5]*m[3]*m[14] + m[13]*m[2]*m[7] - m[13]*m[3]*m[6];
    inv[6] = -m[0]*m[6]*m[15] + m[0]*m[7]*m[14] + m[4]*m[2]*m[15] -
             m[4]*m[3]*m[14] - m[12]*m[2]*m[7] + m[12]*m[3]*m[6];
    inv[10] = m[0]*m[5]*m[15] - m[0]*m[7]*m[13] - m[4]*m[1]*m[15] +
              m[4]*m[3]*m[13] + m[12]*m[1]*m[7] - m[12]*m[3]*m[5];
    inv[14] = -m[0]*m[5]*m[14] + m[0]*m[6]*m[13] + m[4]*m[1]*m[14] -
              m[4]*m[2]*m[13] - m[12]*m[1]*m[6] + m[12]*m[2]*m[5];
    inv[3] = -m[1]*m[6]*m[11] + m[1]*m[7]*m[10] + m[5]*m[2]*m[11] -
             m[5]*m[3]*m[10] - m[9]*m[2]*m[7] + m[9]*m[3]*m[6];
    inv[7] = m[0]*m[6]*m[11] - m[0]*m[7]*m[10] - m[4]*m[2]*m[11] +
             m[4]*m[3]*m[10] + m[8]*m[2]*m[7] - m[8]*m[3]*m[6];
    inv[11] = -m[0]*m[5]*m[11] + m[0]*m[7]*m[9] + m[4]*m[1]*m[11] -
              m[4]*m[3]*m[9] - m[8]*m[1]*m[7] + m[8]*m[3]*m[5];
    inv[15] = m[0]*m[5]*m[10] - m[0]*m[6]*m[9] - m[4]*m[1]*m[10] +
              m[4]*m[2]*m[9] + m[8]*m[1]*m[6] - m[8]*m[2]*m[5];
    float det = m[0]*inv[0] + m[1]*inv[4] + m[2]*inv[8] + m[3]*inv[12];
    det = 1.0f / det;
    for (int i = 0; i < 16; i++) invOut[i] = inv[i] * det;
}

__global__ void setup_kernel(const float* __restrict__ c2w,
                             const float* __restrict__ K,
                             const float* __restrict__ l2w) {
    float inv[16];
    inv4x4(c2w, inv);
    for (int i = 0; i < 12; i++) g_P.w2c[i] = inv[i];
    inv4x4(l2w, inv);
    for (int i = 0; i < 12; i++) g_P.w2l[i] = inv[i];
    g_P.fx = K[0]; g_P.cx = K[2];
    g_P.fy = K[4]; g_P.cy = K[5];
}

// Zero all scratch: CAM_PIX float4 + CAM_PIX/4 float4 (camA) + LID_PIX/2 float4
#define Z_CAM4 CAM_PIX
#define Z_CAMA (CAM_PIX / 4)
#define Z_LID  (LID_PIX / 2)
#define Z_TOT  (Z_CAM4 + Z_CAMA + Z_LID)
__global__ void zero_kernel() {
    int i = blockIdx.x * blockDim.x + threadIdx.x;
    float4 z = make_float4(0.f, 0.f, 0.f, 0.f);
    if (i < Z_CAM4) {
        g_cam4[i] = z;
    } else if (i < Z_CAM4 + Z_CAMA) {
        ((float4*)g_camA)[i - Z_CAM4] = z;
    } else if (i < Z_TOT) {
        ((float4*)g_lid2)[i - Z_CAM4 - Z_CAMA] = z;
    }
}

__device__ __forceinline__ float sigmoid_clip(float x) {
    x = fminf(fmaxf(x, -20.0f), 20.0f);
    return 1.0f / (1.0f + expf(-x));
}

__global__ void splat_kernel(const float* __restrict__ means,
                             const float* __restrict__ sh,
                             const float* __restrict__ opa_c,
                             const float* __restrict__ opa_l, int n) {
    int g = blockIdx.x * blockDim.x + threadIdx.x;
    if (g >= n) return;

    const float mx = means[3*g + 0];
    const float my = means[3*g + 1];
    const float mz = means[3*g + 2];

    // ---------------- camera ----------------
    {
        const float* M = g_P.w2c;
        float x = __fadd_rn(__fadd_rn(__fadd_rn(__fmul_rn(M[0],mx), __fmul_rn(M[1],my)), __fmul_rn(M[2],mz)), M[3]);
        float y = __fadd_rn(__fadd_rn(__fadd_rn(__fmul_rn(M[4],mx), __fmul_rn(M[5],my)), __fmul_rn(M[6],mz)), M[7]);
        float z = __fadd_rn(__fadd_rn(__fadd_rn(__fmul_rn(M[8],mx), __fmul_rn(M[9],my)), __fmul_rn(M[10],mz)), M[11]);
        if (z > NEAR_PLANE && z < FAR_PLANE) {
            float u = __fadd_rn(__fdiv_rn(__fmul_rn(g_P.fx, x), z), g_P.cx);
            float v = __fadd_rn(__fdiv_rn(__fmul_rn(g_P.fy, y), z), g_P.cy);
            float u0 = floorf(u), v0 = floorf(v);
            float fu = __fsub_rn(u, u0), fv = __fsub_rn(v, v0);
            int u0i = (int)u0, v0i = (int)v0;
            if (u0i >= -1 && u0i < W_IMG && v0i >= -1 && v0i < H_IMG) {
                float oc = sigmoid_clip(opa_c[g]);
                float cr = sigmoid_clip(sh[48*g + 0]);
                float cg = sigmoid_clip(sh[48*g + 1]);
                float cb = sigmoid_clip(sh[48*g + 2]);
                float ofu = __fsub_rn(1.0f, fu), ofv = __fsub_rn(1.0f, fv);
                float cw[4] = { __fmul_rn(ofu, ofv), __fmul_rn(fu, ofv),
                                __fmul_rn(ofu, fv),  __fmul_rn(fu, fv) };
                #pragma unroll
                for (int c = 0; c < 4; c++) {
                    int ui = u0i + (c & 1);
                    int vi = v0i + (c >> 1);
                    if (ui >= 0 && ui < W_IMG && vi >= 0 && vi < H_IMG) {
                        float ww = __fmul_rn(oc, cw[c]);
                        int pix = vi * W_IMG + ui;
                        red_add_v4(&g_cam4[pix],
                                   __fmul_rn(cr, ww), __fmul_rn(cg, ww),
                                   __fmul_rn(cb, ww), __fmul_rn(z, ww));
                        atomicAdd(&g_camA[pix], ww);
                    }
                }
            }
        }
    }

    // ---------------- lidar ----------------
    {
        const float* M = g_P.w2l;
        float x = __fadd_rn(__fadd_rn(__fadd_rn(__fmul_rn(M[0],mx), __fmul_rn(M[1],my)), __fmul_rn(M[2],mz)), M[3]);
        float y = __fadd_rn(__fadd_rn(__fadd_rn(__fmul_rn(M[4],mx), __fmul_rn(M[5],my)), __fmul_rn(M[6],mz)), M[7]);
        float z = __fadd_rn(__fadd_rn(__fadd_rn(__fmul_rn(M[8],mx), __fmul_rn(M[9],my)), __fmul_rn(M[10],mz)), M[11]);
        float r = sqrtf(__fadd_rn(__fadd_rn(__fmul_rn(x,x), __fmul_rn(y,y)), __fmul_rn(z,z)));
        if (r > NEAR_PLANE && r < FAR_PLANE) {
            float s = __fdiv_rn(z, fmaxf(r, 1e-6f));
            if (s >= SIN_FMIN_LO && s <= SIN_FMAX_HI) {
                float el = asinf(s);
                if (el >= FMIN_F && el <= FMAX_F) {
                    float az = atan2f(y, x);
                    float uL = __fmul_rn(__fadd_rn(__fdiv_rn(az, TWO_PI_F), 0.5f), (float)WL_IMG);
                    float vL = __fmul_rn(__fdiv_rn(__fsub_rn(FMAX_F, el), FRANGE_F), (float)(HL_IMG - 1));
                    float u0 = floorf(uL), v0 = floorf(vL);
                    float fu = __fsub_rn(uL, u0), fv = __fsub_rn(vL, v0);
                    int u0i = (int)u0, v0i = (int)v0;
                    float ol = sigmoid_clip(opa_l[g]);
                    float ofu = __fsub_rn(1.0f, fu), ofv = __fsub_rn(1.0f, fv);
                    float cw[4] = { __fmul_rn(ofu, ofv), __fmul_rn(fu, ofv),
                                    __fmul_rn(ofu, fv),  __fmul_rn(fu, fv) };
                    #pragma unroll
                    for (int c = 0; c < 4; c++) {
                        int ui = (u0i + (c & 1)) & (WL_IMG - 1);
                        int vi = v0i + (c >> 1);
                        if (vi >= 0 && vi < HL_IMG) {
                            float ww = __fmul_rn(ol, cw[c]);
                            int pix = vi * WL_IMG + ui;
                            red_add_v2(&g_lid2[pix], __fmul_rn(r, ww), ww);
                        }
                    }
                }
            }
        }
    }
}

// Streaming finalize: read scratch, write final planes (4 pixels/thread).
#define CAM_T (CAM_PIX / 4)   // 360,000
#define LID_T (LID_PIX / 4)   // 32,768
__global__ void finalize_kernel(float* __restrict__ out) {
    int t = blockIdx.x * blockDim.x + threadIdx.x;
    if (t < CAM_T) {
        float4 acc[4];
        #pragma unroll
        for (int i = 0; i < 4; i++) acc[i] = g_cam4[4*t + i];
        float4 w4 = ((const float4*)g_camA)[t];
        float w[4] = { w4.x, w4.y, w4.z, w4.w };
        float rgb[12], d[4], a[4];
        #pragma unroll
        for (int i = 0; i < 4; i++) {
            float wpe = __fadd_rn(w[i], EPS);
            a[i] = fminf(fmaxf(w[i], 0.0f), 1.0f);
            float inv = __fdiv_rn(1.0f, wpe);
            float sa = __fmul_rn(inv, 1.0f);
            rgb[3*i+0] = __fmul_rn(__fmul_rn(acc[i].x, sa), a[i]);
            rgb[3*i+1] = __fmul_rn(__fmul_rn(acc[i].y, sa), a[i]);
            rgb[3*i+2] = __fmul_rn(__fmul_rn(acc[i].z, sa), a[i]);
            d[i] = __fmul_rn(acc[i].w, inv);
        }
        float4* rgb4 = (float4*)(out + OFF_RGB);
        float4* dep4 = (float4*)(out + OFF_DEPTH);
        float4* alp4 = (float4*)(out + OFF_ALPHA);
        rgb4[3*t + 0] = make_float4(rgb[0], rgb[1], rgb[2],  rgb[3]);
        rgb4[3*t + 1] = make_float4(rgb[4], rgb[5], rgb[6],  rgb[7]);
        rgb4[3*t + 2] = make_float4(rgb[8], rgb[9], rgb[10], rgb[11]);
        dep4[t] = make_float4(d[0], d[1], d[2], d[3]);
        alp4[t] = make_float4(a[0], a[1], a[2], a[3]);
    } else if (t < CAM_T + LID_T) {
        int j = t - CAM_T;
        float4 p0 = ((const float4*)g_lid2)[2*j + 0];  // (d0,w0,d1,w1)
        float4 p1 = ((const float4*)g_lid2)[2*j + 1];  // (d2,w2,d3,w3)
        float d[4] = { p0.x, p0.z, p1.x, p1.z };
        float w[4] = { p0.y, p0.w, p1.y, p1.w };
        #pragma unroll
        for (int i = 0; i < 4; i++) {
            d[i] = __fdiv_rn(d[i], __fadd_rn(w[i], EPS));
            w[i] = fminf(fmaxf(w[i], 0.0f), 1.0f);
        }
        float4* ld4 = (float4*)(out + OFF_LD);
        float4* la4 = (float4*)(out + OFF_LA);
        ld4[j] = make_float4(d[0], d[1], d[2], d[3]);
        la4[j] = make_float4(w[0], w[1], w[2], w[3]);
    }
}

extern "C" void kernel_launch(void* const* d_in, const int* in_sizes, int n_in,
                              void* d_out, int out_size) {
    const float* means = (const float*)d_in[0];
    const float* sh    = (const float*)d_in[3];
    const float* opa_c = (const float*)d_in[4];
    const float* opa_l = (const float*)d_in[5];
    const float* c2w   = (const float*)d_in[6];
    const float* K     = (const float*)d_in[7];
    const float* l2w   = (const float*)d_in[8];
    float* out = (float*)d_out;

    int n = in_sizes[0] / 3;

    zero_kernel<<<(Z_TOT + 255) / 256, 256>>>();
    setup_kernel<<<1, 1>>>(c2w, K, l2w);
    splat_kernel<<<(n + 255) / 256, 256>>>(means, sh, opa_c, opa_l, n);
    int tot = CAM_T + LID_T;
    finalize_kernel<<<(tot + 255) / 256, 256>>>(out);
}